// round 3
// baseline (speedup 1.0000x reference)
#include <cuda_runtime.h>

// Tsit5 coefficients (fp32)
#define A21 0.161f
#define A31 (-0.008480655492356989f)
#define A32 0.335480655492357f
#define A41 2.8971530571054935f
#define A42 (-6.359448489975075f)
#define A43 4.3622954328695815f
#define A51 5.325864828439257f
#define A52 (-11.748883564062828f)
#define A53 7.4955393428898365f
#define A54 (-0.09249506636175525f)
#define A61 5.86145544294642f
#define A62 (-12.92096931784711f)
#define A63 8.159367898576159f
#define A64 (-0.071584973281401f)
#define A65 (-0.028269050394068383f)
#define B1 0.09646076681806523f
#define B2 0.01f
#define B3 0.4798896504144996f
#define B4 1.379008574103742f
#define B5 (-3.290069515436081f)
#define B6 2.324710524099774f
#define E1 (-0.001780011052225777f)
#define E2 (-0.0008164344596567469f)
#define E3 0.007880878010261995f
#define E4 (-0.1447110071732629f)
#define E5 0.5823571654525552f
#define E6 (-0.45808210592918697f)
#define E7 0.015151515151515152f

#define ATOL 1e-8f
#define RTOL 1e-4f
#define PRED_LEN 32
#define MAX_STEPS 12

// RHS for S and I only; R' = gamma*I and D' = mu*I are factored out analytically.
#define RHS2(Sv, Iv, dS, dI)                   \
    {                                          \
        float _inf = bN * (Sv) * (Iv);         \
        dS = -_inf;                            \
        dI = fmaf(-gm, (Iv), _inf);            \
    }

__global__ void __launch_bounds__(64) sird_kernel(
    const float* __restrict__ x,          // [B,3] beta,gamma,mu
    const float* __restrict__ gp,         // [B,1]
    const float* __restrict__ population, // [B]
    float* __restrict__ out,              // [B,32,4]
    int B)
{
    int b = blockIdx.x * blockDim.x + threadIdx.x;
    if (b >= B) return;

    const float beta  = x[3 * b + 0];
    const float gamma = x[3 * b + 1];
    const float mu    = x[3 * b + 2];
    const float N     = population[b];
    const float bN    = beta / N;
    const float gm    = gamma + mu;

    float S = gp[b] - 100.0f;
    float I = 100.0f;
    float R = 0.0f;
    float D = 0.0f;

    float4* orow = reinterpret_cast<float4*>(out + (size_t)b * (PRED_LEN * 4));
    orow[0] = make_float4(S, I, R, D);

    const float tstep = 32.0f / 31.0f;
    float dt = 0.05f;
    float t  = 0.0f;
    float t1 = tstep;
    int   iv = 0;
    int   scnt = 0;

    // Flat step loop: every lane advances its own interval bookkeeping; warp
    // divergence cost is max over lanes of TOTAL steps, not sum of per-interval maxes.
    while (true) {
        float h = fmaxf(fminf(dt, t1 - t), 1e-9f);

        float k1s, k1i;
        const float I1 = I;
        RHS2(S, I, k1s, k1i);

        float as = fmaf(h, A21 * k1s, S);
        float ai = fmaf(h, A21 * k1i, I);
        const float I2 = ai;
        float k2s, k2i;
        RHS2(as, ai, k2s, k2i);

        as = fmaf(h, fmaf(A32, k2s, A31 * k1s), S);
        ai = fmaf(h, fmaf(A32, k2i, A31 * k1i), I);
        const float I3 = ai;
        float k3s, k3i;
        RHS2(as, ai, k3s, k3i);

        as = fmaf(h, fmaf(A43, k3s, fmaf(A42, k2s, A41 * k1s)), S);
        ai = fmaf(h, fmaf(A43, k3i, fmaf(A42, k2i, A41 * k1i)), I);
        const float I4 = ai;
        float k4s, k4i;
        RHS2(as, ai, k4s, k4i);

        as = fmaf(h, fmaf(A54, k4s, fmaf(A53, k3s, fmaf(A52, k2s, A51 * k1s))), S);
        ai = fmaf(h, fmaf(A54, k4i, fmaf(A53, k3i, fmaf(A52, k2i, A51 * k1i))), I);
        const float I5 = ai;
        float k5s, k5i;
        RHS2(as, ai, k5s, k5i);

        as = fmaf(h, fmaf(A65, k5s, fmaf(A64, k4s, fmaf(A63, k3s, fmaf(A62, k2s, A61 * k1s)))), S);
        ai = fmaf(h, fmaf(A65, k5i, fmaf(A64, k4i, fmaf(A63, k3i, fmaf(A62, k2i, A61 * k1i)))), I);
        const float I6 = ai;
        float k6s, k6i;
        RHS2(as, ai, k6s, k6i);

        float nS = fmaf(h, fmaf(B6, k6s, fmaf(B5, k5s, fmaf(B4, k4s, fmaf(B3, k3s, fmaf(B2, k2s, B1 * k1s))))), S);
        float nI = fmaf(h, fmaf(B6, k6i, fmaf(B5, k5i, fmaf(B4, k4i, fmaf(B3, k3i, fmaf(B2, k2i, B1 * k1i))))), I);
        const float I7 = nI;

        // R/D updates via factored I-stage sums:
        //   k_j^R = gamma*I_j, k_j^D = mu*I_j  =>  nR = R + h*gamma*SB, etc.
        const float SB = fmaf(B6, I6, fmaf(B5, I5, fmaf(B4, I4, fmaf(B3, I3, fmaf(B2, I2, B1 * I1)))));
        const float hg = h * gamma;
        const float hm = h * mu;
        float nR = fmaf(hg, SB, R);
        float nD = fmaf(hm, SB, D);

        float k7s, k7i;
        RHS2(nS, nI, k7s, k7i);

        // error estimates
        float es = h * fmaf(E7, k7s, fmaf(E6, k6s, fmaf(E5, k5s, fmaf(E4, k4s, fmaf(E3, k3s, fmaf(E2, k2s, E1 * k1s))))));
        float ei = h * fmaf(E7, k7i, fmaf(E6, k6i, fmaf(E5, k5i, fmaf(E4, k4i, fmaf(E3, k3i, fmaf(E2, k2i, E1 * k1i))))));
        const float SE = fmaf(E7, I7, fmaf(E6, I6, fmaf(E5, I5, fmaf(E4, I4, fmaf(E3, I3, fmaf(E2, I2, E1 * I1))))));
        float er = hg * SE;
        float ed = hm * SE;

        float ts_ = fmaf(RTOL, fmaxf(fabsf(S), fabsf(nS)), ATOL);
        float ti_ = fmaf(RTOL, fmaxf(fabsf(I), fabsf(nI)), ATOL);
        float tr_ = fmaf(RTOL, fmaxf(fabsf(R), fabsf(nR)), ATOL);
        float td_ = fmaf(RTOL, fmaxf(fabsf(D), fabsf(nD)), ATOL);

        float rs = __fdividef(es, ts_);
        float ri = __fdividef(ei, ti_);
        float rr = __fdividef(er, tr_);
        float rd = __fdividef(ed, td_);
        float enorm2 = 0.25f * (fmaf(rs, rs, ri * ri) + fmaf(rr, rr, rd * rd));

        // fac = clip(0.9 * enorm^-0.2, 0.2, 10);  enorm^-0.2 = (enorm2)^-0.1
        // enorm2 == 0 -> +inf -> clipped to 10 (matches reference clip path).
        float fac = fminf(fmaxf(0.9f * __powf(enorm2, -0.1f), 0.2f), 10.0f);
        dt = h * fac;

        if (enorm2 <= 1.0f) {
            t += h;
            S = nS; I = nI; R = nR; D = nD;
        }
        ++scnt;

        if (t >= t1 - 1e-6f || scnt >= MAX_STEPS) {
            orow[iv + 1] = make_float4(S, I, R, D);
            ++iv;
            if (iv >= PRED_LEN - 1) break;
            t  = (float)iv * tstep;
            t1 = (float)(iv + 1) * tstep;
            scnt = 0;
        }
    }
}

extern "C" void kernel_launch(void* const* d_in, const int* in_sizes, int n_in,
                              void* d_out, int out_size)
{
    const float* x   = (const float*)d_in[0];
    const float* gp  = (const float*)d_in[1];
    const float* pop = (const float*)d_in[2];
    float* out = (float*)d_out;
    int B = in_sizes[2];  // population has B elements

    int threads = 64;  // fine-grained blocks -> even wave distribution over 148 SMs
    int blocks = (B + threads - 1) / threads;
    sird_kernel<<<blocks, threads>>>(x, gp, pop, out, B);
}

// round 4
// speedup vs baseline: 1.4628x; 1.4628x over previous
#include <cuda_runtime.h>

// Tsit5 coefficients (fp32)
#define A21 0.161f
#define A31 (-0.008480655492356989f)
#define A32 0.335480655492357f
#define A41 2.8971530571054935f
#define A42 (-6.359448489975075f)
#define A43 4.3622954328695815f
#define A51 5.325864828439257f
#define A52 (-11.748883564062828f)
#define A53 7.4955393428898365f
#define A54 (-0.09249506636175525f)
#define A61 5.86145544294642f
#define A62 (-12.92096931784711f)
#define A63 8.159367898576159f
#define A64 (-0.071584973281401f)
#define A65 (-0.028269050394068383f)
#define B1 0.09646076681806523f
#define B2 0.01f
#define B3 0.4798896504144996f
#define B4 1.379008574103742f
#define B5 (-3.290069515436081f)
#define B6 2.324710524099774f
#define E1 (-0.001780011052225777f)
#define E2 (-0.0008164344596567469f)
#define E3 0.007880878010261995f
#define E4 (-0.1447110071732629f)
#define E5 0.5823571654525552f
#define E6 (-0.45808210592918697f)
#define E7 0.015151515151515152f

#define ATOL 1e-8f
#define RTOL 1e-4f
#define PRED_LEN 32
#define MAX_STEPS 12

// RHS for S and I only; R' = gamma*I and D' = mu*I are factored out analytically.
#define RHS2(Sv, Iv, dS, dI)                   \
    {                                          \
        float _inf = bN * (Sv) * (Iv);         \
        dS = -_inf;                            \
        dI = fmaf(-gm, (Iv), _inf);            \
    }

__global__ void __launch_bounds__(128) sird_kernel(
    const float* __restrict__ x,          // [B,3] beta,gamma,mu
    const float* __restrict__ gp,         // [B,1]
    const float* __restrict__ population, // [B]
    float* __restrict__ out,              // [B,32,4]
    int B)
{
    int b = blockIdx.x * blockDim.x + threadIdx.x;
    if (b >= B) return;

    const float beta  = x[3 * b + 0];
    const float gamma = x[3 * b + 1];
    const float mu    = x[3 * b + 2];
    const float N     = population[b];
    const float bN    = beta / N;
    const float gm    = gamma + mu;

    float S = gp[b] - 100.0f;
    float I = 100.0f;
    float R = 0.0f;
    float D = 0.0f;

    float4* orow = reinterpret_cast<float4*>(out + (size_t)b * (PRED_LEN * 4));
    orow[0] = make_float4(S, I, R, D);

    float dt = 0.05f;
    const float tstep = 32.0f / 31.0f;

    for (int iv = 0; iv < PRED_LEN - 1; ++iv) {
        const float t1 = (float)(iv + 1) * tstep;
        float t = (float)iv * tstep;

        for (int s = 0; s < MAX_STEPS; ++s) {
            float h = fmaxf(fminf(dt, t1 - t), 1e-9f);

            float k1s, k1i;
            const float I1 = I;
            RHS2(S, I, k1s, k1i);

            float as = fmaf(h, A21 * k1s, S);
            float ai = fmaf(h, A21 * k1i, I);
            const float I2 = ai;
            float k2s, k2i;
            RHS2(as, ai, k2s, k2i);

            as = fmaf(h, fmaf(A32, k2s, A31 * k1s), S);
            ai = fmaf(h, fmaf(A32, k2i, A31 * k1i), I);
            const float I3 = ai;
            float k3s, k3i;
            RHS2(as, ai, k3s, k3i);

            as = fmaf(h, fmaf(A43, k3s, fmaf(A42, k2s, A41 * k1s)), S);
            ai = fmaf(h, fmaf(A43, k3i, fmaf(A42, k2i, A41 * k1i)), I);
            const float I4 = ai;
            float k4s, k4i;
            RHS2(as, ai, k4s, k4i);

            as = fmaf(h, fmaf(A54, k4s, fmaf(A53, k3s, fmaf(A52, k2s, A51 * k1s))), S);
            ai = fmaf(h, fmaf(A54, k4i, fmaf(A53, k3i, fmaf(A52, k2i, A51 * k1i))), I);
            const float I5 = ai;
            float k5s, k5i;
            RHS2(as, ai, k5s, k5i);

            as = fmaf(h, fmaf(A65, k5s, fmaf(A64, k4s, fmaf(A63, k3s, fmaf(A62, k2s, A61 * k1s)))), S);
            ai = fmaf(h, fmaf(A65, k5i, fmaf(A64, k4i, fmaf(A63, k3i, fmaf(A62, k2i, A61 * k1i)))), I);
            const float I6 = ai;
            float k6s, k6i;
            RHS2(as, ai, k6s, k6i);

            float nS = fmaf(h, fmaf(B6, k6s, fmaf(B5, k5s, fmaf(B4, k4s, fmaf(B3, k3s, fmaf(B2, k2s, B1 * k1s))))), S);
            float nI = fmaf(h, fmaf(B6, k6i, fmaf(B5, k5i, fmaf(B4, k4i, fmaf(B3, k3i, fmaf(B2, k2i, B1 * k1i))))), I);
            const float I7 = nI;

            // R/D via factored I-stage sums: k_j^R = gamma*I_j, k_j^D = mu*I_j
            const float SB = fmaf(B6, I6, fmaf(B5, I5, fmaf(B4, I4, fmaf(B3, I3, fmaf(B2, I2, B1 * I1)))));
            const float hg = h * gamma;
            const float hm = h * mu;
            float nR = fmaf(hg, SB, R);
            float nD = fmaf(hm, SB, D);

            float k7s, k7i;
            RHS2(nS, nI, k7s, k7i);

            // error estimates
            float es = h * fmaf(E7, k7s, fmaf(E6, k6s, fmaf(E5, k5s, fmaf(E4, k4s, fmaf(E3, k3s, fmaf(E2, k2s, E1 * k1s))))));
            float ei = h * fmaf(E7, k7i, fmaf(E6, k6i, fmaf(E5, k5i, fmaf(E4, k4i, fmaf(E3, k3i, fmaf(E2, k2i, E1 * k1i))))));
            const float SE = fmaf(E7, I7, fmaf(E6, I6, fmaf(E5, I5, fmaf(E4, I4, fmaf(E3, I3, fmaf(E2, I2, E1 * I1))))));
            float er = hg * SE;
            float ed = hm * SE;

            float ts_ = fmaf(RTOL, fmaxf(fabsf(S), fabsf(nS)), ATOL);
            float ti_ = fmaf(RTOL, fmaxf(fabsf(I), fabsf(nI)), ATOL);
            float tr_ = fmaf(RTOL, fmaxf(fabsf(R), fabsf(nR)), ATOL);
            float td_ = fmaf(RTOL, fmaxf(fabsf(D), fabsf(nD)), ATOL);

            float rs = __fdividef(es, ts_);
            float ri = __fdividef(ei, ti_);
            float rr = __fdividef(er, tr_);
            float rd = __fdividef(ed, td_);
            float enorm2 = 0.25f * (fmaf(rs, rs, ri * ri) + fmaf(rr, rr, rd * rd));

            // fac = clip(0.9 * enorm^-0.2, 0.2, 10);  enorm^-0.2 = (enorm2)^-0.1
            // enorm2 == 0 -> +inf -> clipped to 10 (matches reference clip path).
            float fac = fminf(fmaxf(0.9f * __powf(enorm2, -0.1f), 0.2f), 10.0f);
            dt = h * fac;

            if (enorm2 <= 1.0f) {
                t += h;
                S = nS; I = nI; R = nR; D = nD;
            }
            if (t >= t1 - 1e-6f) break;
        }

        orow[iv + 1] = make_float4(S, I, R, D);
    }
}

extern "C" void kernel_launch(void* const* d_in, const int* in_sizes, int n_in,
                              void* d_out, int out_size)
{
    const float* x   = (const float*)d_in[0];
    const float* gp  = (const float*)d_in[1];
    const float* pop = (const float*)d_in[2];
    float* out = (float*)d_out;
    int B = in_sizes[2];  // population has B elements

    int threads = 128;
    int blocks = (B + threads - 1) / threads;
    sird_kernel<<<blocks, threads>>>(x, gp, pop, out, B);
}